// round 17
// baseline (speedup 1.0000x reference)
#include <cuda_runtime.h>
#include <cuda_bf16.h>
#include <cstdint>

#define N_NODES 100000
#define N_EDGES 1600000
#define D 32
#define ED 8
#define FULL 0xffffffffu
#define UN 4                 // 4-edge groups per tile -> 16 edges per warp-iter
#define TILE (UN * 4)        // N_EDGES % 16 == 0

// f32x2 packed-math helpers (PTX-only; ptxas never fuses these from C++).
#define PACKF2(out, lo, hi) \
    asm("mov.b64 %0, {%1, %2};" : "=l"(out) \
        : "r"(__float_as_uint(lo)), "r"(__float_as_uint(hi)))
#define FMA_F32X2(d, a, b, c) \
    asm("fma.rn.f32x2 %0, %1, %2, %3;" : "=l"(d) : "l"(a), "l"(b), "l"(c))
#define UNPACKF2(lo, hi, in) do { \
    uint32_t _l, _h; \
    asm("mov.b64 {%0, %1}, %2;" : "=r"(_l), "=r"(_h) : "l"(in)); \
    (lo) = __uint_as_float(_l); (hi) = __uint_as_float(_h); } while (0)

// Ping-pong node features + per-layer aggregation buffers (memset once).
__device__ float g_buf0[N_NODES * D];
__device__ float g_buf1[N_NODES * D];
__device__ float g_agg[3][N_NODES * D];

// ---------------------------------------------------------------------------
// Edge kernel (R14/R16, measured best at ~50.8us/layer): 16 edges per
// warp-iteration, 4 independent 4-edge groups (MLP=4 gathers/REDs),
// next-tile idx prefetch, f32x2 packed FMA embedding loop.
//   lane layout: g = lane>>3 edge-in-quad, c = lane&7 column quad.
// edge_attr / edge_index read once per layer -> __ldcs (evict-first).
// Persistent grid: 592 blocks (4/SM, single wave), strided tile loop.
// ---------------------------------------------------------------------------
__global__ __launch_bounds__(128, 4) void edge_kernel(
    const float* __restrict__ x_ext, int x_sel, int layer,
    const float* __restrict__ edge_attr,
    const float* __restrict__ We,   // layer slice: [8, 32]
    const float* __restrict__ be,   // layer slice: [32]
    const int*   __restrict__ edge_index)  // [2, E]: src rows then dst rows
{
    const float* x = (x_sel == 0) ? x_ext : (x_sel == 1 ? g_buf0 : g_buf1);
    float* agg = &g_agg[layer][0];

    const int lane = threadIdx.x & 31;
    const int c    = lane & 7;
    const int g    = lane >> 3;
    const int wid  = (blockIdx.x * blockDim.x + threadIdx.x) >> 5;
    const int nw   = (gridDim.x * blockDim.x) >> 5;

    // Weight column quads as packed f32x2 pairs: (x,y) and (z,w) per k.
    uint64_t wxy[ED], wzw[ED];
#pragma unroll
    for (int k = 0; k < ED; k++) {
        const float4 wv = *reinterpret_cast<const float4*>(We + k * D + c * 4);
        PACKF2(wxy[k], wv.x, wv.y);
        PACKF2(wzw[k], wv.z, wv.w);
    }
    uint64_t bxy, bzw;
    {
        const float4 bv = *reinterpret_cast<const float4*>(be + c * 4);
        PACKF2(bxy, bv.x, bv.y);
        PACKF2(bzw, bv.z, bv.w);
    }

    int e = wid * TILE;
    if (e >= N_EDGES) return;

    // lanes 0-15: src[e+lane]; lanes 16-31: dst[e+lane-16]
    const int idx_off = (lane < 16) ? lane : (N_EDGES - 16 + lane);

    // Prologue: first tile's indices in ONE streaming load.
    int s[UN], d[UN];
    {
        const int iv = __ldcs(edge_index + e + idx_off);
#pragma unroll
        for (int u = 0; u < UN; u++) {
            s[u] = __shfl_sync(FULL, iv, u * 4 + g);
            d[u] = __shfl_sync(FULL, iv, 16 + u * 4 + g);
        }
    }

    const int stride = nw * TILE;
    for (; e < N_EDGES; e += stride) {
        // 4 independent gathers issue immediately (indices resident).
        float4 xv[UN];
#pragma unroll
        for (int u = 0; u < UN; u++)
            xv[u] = __ldg(reinterpret_cast<const float4*>(
                x + (size_t)s[u] * D + c * 4));

        // Whole tile's 128 attr floats in one streaming LDG.128 (lane owns 4).
        const float4 av4 = __ldcs(
            reinterpret_cast<const float4*>(edge_attr + (size_t)e * ED) + lane);

        // Prefetch next tile's indices (wrapped on last iteration).
        const int ne = e + stride;
        const int nc = (ne < N_EDGES) ? ne : 0;
        const int niv = __ldcs(edge_index + nc + idx_off);

        // Packed-FMA embedding: a[u] = be + sum_k attr_k * We[k]
        // attr k of edge (4u+g) lives in lane 8u+2g+(k>>2), component k&3.
        uint64_t axy[UN], azw[UN];
#pragma unroll
        for (int u = 0; u < UN; u++) { axy[u] = bxy; azw[u] = bzw; }
#pragma unroll
        for (int k = 0; k < ED; k++) {
            const float comp = ((k & 3) == 0) ? av4.x
                             : ((k & 3) == 1) ? av4.y
                             : ((k & 3) == 2) ? av4.z : av4.w;
#pragma unroll
            for (int u = 0; u < UN; u++) {
                const float f =
                    __shfl_sync(FULL, comp, u * 8 + g * 2 + (k >> 2));
                uint64_t pf;
                PACKF2(pf, f, f);
                FMA_F32X2(axy[u], pf, wxy[k], axy[u]);
                FMA_F32X2(azw[u], pf, wzw[k], azw[u]);
            }
        }

#pragma unroll
        for (int u = 0; u < UN; u++) {
            float ax, ay, az, aw;
            UNPACKF2(ax, ay, axy[u]);
            UNPACKF2(az, aw, azw[u]);
            float4 m;
            m.x = fmaxf(xv[u].x + ax, 0.0f);
            m.y = fmaxf(xv[u].y + ay, 0.0f);
            m.z = fmaxf(xv[u].z + az, 0.0f);
            m.w = fmaxf(xv[u].w + aw, 0.0f);
            float* p = agg + (size_t)d[u] * D + c * 4;
            asm volatile("red.global.add.v4.f32 [%0], {%1,%2,%3,%4};"
                         :: "l"(p), "f"(m.x), "f"(m.y), "f"(m.z), "f"(m.w)
                         : "memory");
        }

        // Extract next tile's ids for the next iteration.
#pragma unroll
        for (int u = 0; u < UN; u++) {
            s[u] = __shfl_sync(FULL, niv, u * 4 + g);
            d[u] = __shfl_sync(FULL, niv, 16 + u * 4 + g);
        }
    }
}

// ---------------------------------------------------------------------------
// Node kernel (R15/R16, measured best): 2 nodes per warp, f32x2 FMAs,
// unrolled x2 (4 nodes per warp-iteration -> MLP=2 on x/agg loads).
// ---------------------------------------------------------------------------
__global__ __launch_bounds__(128) void node_kernel(
    const float* __restrict__ x_ext, int x_sel, int layer,
    float* __restrict__ out_ext, int out_sel,
    const float* __restrict__ W,    // [32, 32]
    const float* __restrict__ b)    // [32]
{
    const float* x  = (x_sel == 0) ? x_ext : (x_sel == 1 ? g_buf0 : g_buf1);
    float* out = (out_sel == 0) ? out_ext : (out_sel == 1 ? g_buf0 : g_buf1);
    const float* agg = &g_agg[layer][0];

    const int lane = threadIdx.x & 31;
    const int c2   = lane & 15;     // column pair: cols 2c2, 2c2+1
    const int gn   = lane >> 4;     // node within a pair
    const int wid  = (blockIdx.x * blockDim.x + threadIdx.x) >> 5;
    const int nw   = (gridDim.x * blockDim.x) >> 5;

    uint64_t w2[D];
#pragma unroll
    for (int k = 0; k < D; k++) {
        const float2 wv = *reinterpret_cast<const float2*>(W + k * D + c2 * 2);
        PACKF2(w2[k], wv.x, wv.y);
    }
    uint64_t b2;
    {
        const float2 bv = *reinterpret_cast<const float2*>(b + c2 * 2);
        PACKF2(b2, bv.x, bv.y);
    }

    // N_NODES % 4 == 0: each warp-iteration covers 4 full nodes.
    for (int n4 = wid * 4; n4 < N_NODES; n4 += nw * 4) {
        const int nodeA = n4 + gn;
        const int nodeB = n4 + 2 + gn;

        const float2 xvA = *reinterpret_cast<const float2*>(
            x + (size_t)nodeA * D + c2 * 2);
        const float2 agA = __ldcs(reinterpret_cast<const float2*>(
            agg + (size_t)nodeA * D + c2 * 2));
        const float2 xvB = *reinterpret_cast<const float2*>(
            x + (size_t)nodeB * D + c2 * 2);
        const float2 agB = __ldcs(reinterpret_cast<const float2*>(
            agg + (size_t)nodeB * D + c2 * 2));

        const float hA0 = xvA.x + agA.x, hA1 = xvA.y + agA.y;
        const float hB0 = xvB.x + agB.x, hB1 = xvB.y + agB.y;

        uint64_t accA = b2, accB = b2;
#pragma unroll
        for (int k = 0; k < D; k++) {
            const float hkA = (k & 1) ? hA1 : hA0;
            const float hkB = (k & 1) ? hB1 : hB0;
            const float fA = __shfl_sync(FULL, hkA, (gn << 4) + (k >> 1));
            const float fB = __shfl_sync(FULL, hkB, (gn << 4) + (k >> 1));
            uint64_t pA, pB;
            PACKF2(pA, fA, fA);
            PACKF2(pB, fB, fB);
            FMA_F32X2(accA, pA, w2[k], accA);
            FMA_F32X2(accB, pB, w2[k], accB);
        }
        float a0, a1, b0, b1;
        UNPACKF2(a0, a1, accA);
        UNPACKF2(b0, b1, accB);
        float2 oA, oB;
        oA.x = fmaxf(a0, 0.01f * a0);   // leaky_relu 0.01
        oA.y = fmaxf(a1, 0.01f * a1);
        oB.x = fmaxf(b0, 0.01f * b0);
        oB.y = fmaxf(b1, 0.01f * b1);
        *reinterpret_cast<float2*>(out + (size_t)nodeA * D + c2 * 2) = oA;
        *reinterpret_cast<float2*>(out + (size_t)nodeB * D + c2 * 2) = oB;
    }
}

// ---------------------------------------------------------------------------
extern "C" void kernel_launch(void* const* d_in, const int* in_sizes, int n_in,
                              void* d_out, int out_size)
{
    const float* x   = (const float*)d_in[0];   // [N, 32]
    const float* ea  = (const float*)d_in[1];   // [E, 8]
    const float* W   = (const float*)d_in[2];   // [3, 32, 32]
    const float* b   = (const float*)d_in[3];   // [3, 32]
    const float* We  = (const float*)d_in[4];   // [3, 8, 32]
    const float* be  = (const float*)d_in[5];   // [3, 32]
    const int*   ei  = (const int*)d_in[6];     // [2, E] int32
    float* out = (float*)d_out;

    const int x_sels[3]   = {0, 1, 2};
    const int out_sels[3] = {1, 2, 0};

    // Zero the agg buffers with the driver memset path (graph memset node;
    // no allocation — symbol address of a static __device__ array).
    void* agg_ptr = nullptr;
    cudaGetSymbolAddress(&agg_ptr, g_agg);
    cudaMemsetAsync(agg_ptr, 0, sizeof(float) * 3 * N_NODES * D);

    for (int l = 0; l < 3; l++) {
        edge_kernel<<<592, 128>>>(   // persistent: 4 blocks/SM, single wave
            x, x_sels[l], l, ea, We + l * ED * D, be + l * D, ei);
        node_kernel<<<1184, 128>>>(
            x, x_sels[l], l, out, out_sels[l], W + l * D * D, b + l * D);
    }
}